// round 14
// baseline (speedup 1.0000x reference)
#include <cuda_runtime.h>
#include <cstdint>

// ---------------- problem dims ----------------
#define BB 64
#define TT 1024
#define FF 256
#define HH 1024
#define G4 4096
#define OO 256
#define HB (HH * BB)

#define NCTA 128           // persistent CTAs for recurrence (1/SM via SMEM, <=148)
#define JPER 8             // hidden units per CTA (1024/128)

// ---------------- scratch (static device memory only; no allocs) ----------------
__device__ float g_tmp[(size_t)BB * TT * FF];                 // 64 MB  blur pass1
__device__ float g_xb [(size_t)BB * TT * FF];                 // 64 MB  blurred input
__device__ float g_xg [(size_t)BB * TT * G4];                 // 1 GB   gate preactivations (+biases)
__device__ float g_h  [2 * HB];                               // h double buffer, layout [buf][b][k]
__device__ unsigned g_bar;                                    // grid barrier counter (cumulative)

__constant__ float c_w9[9] = {
    1.3383062e-4f, 4.4318616e-3f, 5.3991124e-2f, 2.4197145e-1f,
    3.9894347e-1f,
    2.4197145e-1f, 5.3991124e-2f, 4.4318616e-3f, 1.3383062e-4f
};

// ---------------- helpers ----------------
__device__ __forceinline__ uint32_t f2tf(float x) {           // round-to-nearest tf32
    uint32_t u;
    asm("cvt.rna.tf32.f32 %0, %1;" : "=r"(u) : "f"(x));
    return u;
}
__device__ __forceinline__ void mma_tf32(float* d, uint32_t a0, uint32_t a1,
                                         uint32_t a2, uint32_t a3,
                                         uint32_t b0, uint32_t b1) {
    asm volatile(
        "mma.sync.aligned.m16n8k8.row.col.f32.tf32.tf32.f32 "
        "{%0,%1,%2,%3}, {%4,%5,%6,%7}, {%8,%9}, {%0,%1,%2,%3};"
        : "+f"(d[0]), "+f"(d[1]), "+f"(d[2]), "+f"(d[3])
        : "r"(a0), "r"(a1), "r"(a2), "r"(a3), "r"(b0), "r"(b1));
}
__device__ __forceinline__ void cp16(uint32_t smem_addr, const void* gptr) {
    asm volatile("cp.async.cg.shared.global [%0], [%1], 16;" ::
                 "r"(smem_addr), "l"(gptr));
}

// ---------------- init: zero h0, reset barrier ----------------
__global__ void init_kernel() {
    int i = blockIdx.x * 256 + threadIdx.x;
    if (i < HB) g_h[i] = 0.f;
    if (i == 0) g_bar = 0u;
}

// ---------------- blur time axis ----------------
__global__ void __launch_bounds__(256) blur_t_kernel(const float* __restrict__ x) {
    int idx = blockIdx.x * 256 + threadIdx.x;
    int f = idx & (FF - 1);
    int t = (idx >> 8) & (TT - 1);
    int b = idx >> 18;
    const float* base = x + (size_t)b * TT * FF + f;
    float s = 0.f;
#pragma unroll
    for (int k = 0; k < 9; ++k) {
        int ts = t + k - 4;
        ts = ts < 0 ? 0 : (ts > TT - 1 ? TT - 1 : ts);
        s += c_w9[k] * base[(size_t)ts * FF];
    }
    g_tmp[idx] = s;
}

// ---------------- blur feature axis ----------------
__global__ void __launch_bounds__(256) blur_f_kernel() {
    int idx = blockIdx.x * 256 + threadIdx.x;
    int f = idx & (FF - 1);
    int rowbase = idx - f;
    float s = 0.f;
#pragma unroll
    for (int k = 0; k < 9; ++k) {
        int fs = f + k - 4;
        fs = fs < 0 ? 0 : (fs > FF - 1 ? FF - 1 : fs);
        s += c_w9[k] * g_tmp[rowbase + fs];
    }
    g_xb[idx] = s;
}

// ---------------- xg = xb @ W_ih^T + (b_ih + b_hh), tf32 mma ----------------
// CTA tile 128(m) x 128(n), K=256 in 4 k-tiles of 64. SMEM [row][k] stride 68.
#define GSTR 68
#define GEMM_SMEM (2 * 128 * GSTR * 4)

__global__ void __launch_bounds__(256, 1) gemm_xg_kernel(const float* __restrict__ Wih,
                                                         const float* __restrict__ bih,
                                                         const float* __restrict__ bhh) {
    extern __shared__ float gsm[];
    float* As = gsm;                   // [128][68]
    float* Bs = gsm + 128 * GSTR;      // [128][68]

    const int tid = threadIdx.x;
    const int wrp = tid >> 5, lane = tid & 31;
    const int g = lane >> 2, tig = lane & 3;
    const int ms = wrp & 1, ns = wrp >> 1;
    const int m0 = blockIdx.y * 128;
    const int n0 = blockIdx.x * 128;

    float d[4][4][4];
#pragma unroll
    for (int a = 0; a < 4; ++a)
#pragma unroll
        for (int b = 0; b < 4; ++b)
#pragma unroll
            for (int c = 0; c < 4; ++c) d[a][b][c] = 0.f;

    for (int kt = 0; kt < 4; ++kt) {
        __syncthreads();
#pragma unroll
        for (int p = 0; p < 8; ++p) {
            int idx = p * 256 + tid;               // 2048 float4 units
            int row = idx >> 4, kq = idx & 15;
            float4 va = *(const float4*)&g_xb[(size_t)(m0 + row) * 256 + kt * 64 + kq * 4];
            float4 vb = *(const float4*)&Wih[(size_t)(n0 + row) * 256 + kt * 64 + kq * 4];
            float* pa = &As[row * GSTR + kq * 4];
            pa[0] = __uint_as_float(f2tf(va.x)); pa[1] = __uint_as_float(f2tf(va.y));
            pa[2] = __uint_as_float(f2tf(va.z)); pa[3] = __uint_as_float(f2tf(va.w));
            float* pb = &Bs[row * GSTR + kq * 4];
            pb[0] = __uint_as_float(f2tf(vb.x)); pb[1] = __uint_as_float(f2tf(vb.y));
            pb[2] = __uint_as_float(f2tf(vb.z)); pb[3] = __uint_as_float(f2tf(vb.w));
        }
        __syncthreads();

#pragma unroll
        for (int sc = 0; sc < 2; ++sc) {
            const int kb = sc * 32;
            uint32_t bv[4][8];
#pragma unroll
            for (int nt = 0; nt < 4; ++nt) {
                const float* wp = &Bs[(ns * 32 + nt * 8 + g) * GSTR + kb + 8 * tig];
                *(uint4*)&bv[nt][0] = *(const uint4*)wp;
                *(uint4*)&bv[nt][4] = *(const uint4*)(wp + 4);
            }
#pragma unroll
            for (int mt = 0; mt < 4; ++mt) {
                const float* alo = &As[(ms * 64 + mt * 16 + g) * GSTR + kb + 8 * tig];
                uint32_t al[8], ah[8];
                *(uint4*)&al[0] = *(const uint4*)alo;
                *(uint4*)&al[4] = *(const uint4*)(alo + 4);
                *(uint4*)&ah[0] = *(const uint4*)(alo + 8 * GSTR);
                *(uint4*)&ah[4] = *(const uint4*)(alo + 8 * GSTR + 4);
#pragma unroll
                for (int c = 0; c < 4; ++c)
#pragma unroll
                    for (int nt = 0; nt < 4; ++nt)
                        mma_tf32(d[mt][nt], al[2 * c], ah[2 * c], al[2 * c + 1], ah[2 * c + 1],
                                 bv[nt][2 * c], bv[nt][2 * c + 1]);
            }
        }
    }

    // epilogue: bias + store
#pragma unroll
    for (int nt = 0; nt < 4; ++nt) {
        int n = n0 + ns * 32 + nt * 8 + 2 * tig;
        float bia0 = bih[n] + bhh[n];
        float bia1 = bih[n + 1] + bhh[n + 1];
#pragma unroll
        for (int mt = 0; mt < 4; ++mt) {
            int m = m0 + ms * 64 + mt * 16 + g;
            float2 r0 = make_float2(d[mt][nt][0] + bia0, d[mt][nt][1] + bia1);
            float2 r1 = make_float2(d[mt][nt][2] + bia0, d[mt][nt][3] + bia1);
            *(float2*)&g_xg[(size_t)m * G4 + n]       = r0;
            *(float2*)&g_xg[(size_t)(m + 8) * G4 + n] = r1;
        }
    }
}

// ---------------- persistent LSTM recurrence (tf32 mma) ----------------
// CTA c owns 8 hidden units -> 32 gate rows. Warps: ks = wrp>>1 (k-split 4),
// ms = wrp&1 (batch-split 2). Warp tile: 32(batch) x 32(gates), k-range 256.
// h global layout [b][k] (tf32-rounded). hs staged [b][k_local] stride 132.
// Wsh [n(32)][k(1024)] stride 1028. red [ks(4)][b(64)][n(32)] stride 40 (alias buf0).
#define WSTR 1028
#define HSTR 132
#define RSTR 40
#define BUFV 10240                                 // floats per h stage buffer
#define WSH_FLOATS (32 * WSTR)                     // 32896
#define LSTM_SMEM ((WSH_FLOATS + 2 * BUFV) * 4)    // 213504 B

__global__ void __launch_bounds__(256, 1) lstm_kernel(const float* __restrict__ Whh) {
    extern __shared__ __align__(16) float sm[];
    float* Wsh  = sm;
    float* bufs = sm + WSH_FLOATS;                 // two BUFV buffers
    float* red  = bufs;                            // aliases buf0

    const int tid  = threadIdx.x;
    const int lane = tid & 31, wrp = tid >> 5;
    const int g = lane >> 2, tig = lane & 3;
    const int ks = wrp >> 1, ms = wrp & 1;
    const int j0 = blockIdx.x * JPER;

    // one-time: W slice -> SMEM [n][k], tf32-rounded
    for (int i = tid; i < 32 * 1024; i += 256) {
        int n = i >> 10, k = i & 1023;
        int q = n >> 3, jj = n & 7;
        Wsh[n * WSTR + k] = __uint_as_float(f2tf(Whh[(size_t)(q * HH + j0 + jj) * HH + k]));
    }
    __syncthreads();

    float cst[2] = {0.f, 0.f};
    const int cell0 = tid * 2;
    const int jj0 = cell0 >> 6, b0 = cell0 & 63;   // cell1 = (jj0, b0+1)

    for (int t = 0; t < TT; ++t) {
        const float* hbuf = g_h + (size_t)(t & 1) * HB;
        float* hout       = g_h + (size_t)((t + 1) & 1) * HB;

        // prefetch xg for this step's cells
        float xgv[2][4];
#pragma unroll
        for (int cc = 0; cc < 2; ++cc)
#pragma unroll
            for (int q = 0; q < 4; ++q)
                xgv[cc][q] = g_xg[((size_t)(b0 + cc) * TT + t) * G4 + q * HH + j0 + jj0];

        float d[2][4][4];
#pragma unroll
        for (int a = 0; a < 2; ++a)
#pragma unroll
            for (int b = 0; b < 4; ++b)
#pragma unroll
                for (int c = 0; c < 4; ++c) d[a][b][c] = 0.f;

        // stage chunk 0
        {
#pragma unroll
            for (int p = 0; p < 8; ++p) {
                int idx = p * 256 + tid;
                int b = idx >> 5, kq = idx & 31;
                uint32_t dst = (uint32_t)__cvta_generic_to_shared(&bufs[b * HSTR + kq * 4]);
                cp16(dst, hbuf + (size_t)b * HH + kq * 4);
            }
            asm volatile("cp.async.commit_group;");
        }

        for (int ch = 0; ch < 8; ++ch) {
            asm volatile("cp.async.wait_group 0;");
            __syncthreads();
            if (ch < 7) {
                float* nbuf = bufs + ((ch + 1) & 1) * BUFV;
#pragma unroll
                for (int p = 0; p < 8; ++p) {
                    int idx = p * 256 + tid;
                    int b = idx >> 5, kq = idx & 31;
                    uint32_t dst = (uint32_t)__cvta_generic_to_shared(&nbuf[b * HSTR + kq * 4]);
                    cp16(dst, hbuf + (size_t)b * HH + (ch + 1) * 128 + kq * 4);
                }
                asm volatile("cp.async.commit_group;");
            }
            // compute on buf[ch&1], warp k-range = ks*32 within the 128-chunk
            const float* buf = bufs + (ch & 1) * BUFV;
            const int kb = ks * 32;
            const int kgl = ch * 128 + kb;

            uint32_t bv[4][8];
#pragma unroll
            for (int nt = 0; nt < 4; ++nt) {
                const float* wp = &Wsh[(nt * 8 + g) * WSTR + kgl + 8 * tig];
                *(uint4*)&bv[nt][0] = *(const uint4*)wp;
                *(uint4*)&bv[nt][4] = *(const uint4*)(wp + 4);
            }
#pragma unroll
            for (int mt = 0; mt < 2; ++mt) {
                const float* alo = &buf[(ms * 32 + mt * 16 + g) * HSTR + kb + 8 * tig];
                uint32_t al[8], ah[8];
                *(uint4*)&al[0] = *(const uint4*)alo;
                *(uint4*)&al[4] = *(const uint4*)(alo + 4);
                *(uint4*)&ah[0] = *(const uint4*)(alo + 8 * HSTR);
                *(uint4*)&ah[4] = *(const uint4*)(alo + 8 * HSTR + 4);
#pragma unroll
                for (int c = 0; c < 4; ++c)
#pragma unroll
                    for (int nt = 0; nt < 4; ++nt)
                        mma_tf32(d[mt][nt], al[2 * c], ah[2 * c], al[2 * c + 1], ah[2 * c + 1],
                                 bv[nt][2 * c], bv[nt][2 * c + 1]);
            }
        }
        __syncthreads();                           // all buf reads done (incl. buf0)

        // write partials to red[ks][b][n]
#pragma unroll
        for (int mt = 0; mt < 2; ++mt)
#pragma unroll
            for (int nt = 0; nt < 4; ++nt) {
                int m = ms * 32 + mt * 16 + g;
                int n = nt * 8 + 2 * tig;
                float* base = &red[(ks * 64 + m) * RSTR + n];
                *(float2*)base              = make_float2(d[mt][nt][0], d[mt][nt][1]);
                *(float2*)(base + 8 * RSTR) = make_float2(d[mt][nt][2], d[mt][nt][3]);
            }
        __syncthreads();

        // gates: 2 cells per thread
#pragma unroll
        for (int cc = 0; cc < 2; ++cc) {
            int b = b0 + cc;
            float gp[4];
#pragma unroll
            for (int q = 0; q < 4; ++q) {
                float s = 0.f;
#pragma unroll
                for (int kss = 0; kss < 4; ++kss)
                    s += red[(kss * 64 + b) * RSTR + q * 8 + jj0];
                gp[q] = s + xgv[cc][q];
            }
            float iv = 1.f / (1.f + expf(-gp[0]));
            float fv = 1.f / (1.f + expf(-gp[1]));
            float gv = tanhf(gp[2]);
            float ov = 1.f / (1.f + expf(-gp[3]));
            float cnew = fv * cst[cc] + iv * gv;
            cst[cc] = cnew;
            float hval = ov * tanhf(cnew);
            hout[(size_t)b * HH + j0 + jj0] = __uint_as_float(f2tf(hval));
        }

        // grid barrier
        __syncthreads();
        if (tid == 0) {
            __threadfence();
            atomicAdd(&g_bar, 1u);
            unsigned target = (unsigned)(t + 1) * (unsigned)NCTA;
            while (atomicAdd(&g_bar, 0u) < target) { __nanosleep(64); }
            __threadfence();
        }
        __syncthreads();
    }
}

// ---------------- out = h_last @ W_fc^T + b_fc ----------------
__global__ void __launch_bounds__(256) fc_kernel(const float* __restrict__ Wfc,
                                                 const float* __restrict__ bfc,
                                                 float* __restrict__ out) {
    __shared__ float hsm[HH];
    const int b = blockIdx.x;
    const int tid = threadIdx.x;
    const float* hbuf = g_h;                       // final h in buffer 0 (T even), [b][k]
    for (int k = tid; k < HH; k += 256) hsm[k] = hbuf[(size_t)b * HH + k];
    __syncthreads();
    const int wrp = tid >> 5, lane = tid & 31;
    for (int o = wrp; o < OO; o += 8) {
        float s = 0.f;
        for (int k = lane; k < HH; k += 32) s += hsm[k] * Wfc[(size_t)o * HH + k];
#pragma unroll
        for (int off = 16; off; off >>= 1) s += __shfl_xor_sync(0xffffffffu, s, off);
        if (lane == 0) out[b * OO + o] = s + bfc[o];
    }
}

// ---------------- launch ----------------
extern "C" void kernel_launch(void* const* d_in, const int* in_sizes, int n_in,
                              void* d_out, int out_size) {
    const float* x    = (const float*)d_in[0];
    const float* W_ih = (const float*)d_in[1];
    const float* W_hh = (const float*)d_in[2];
    const float* b_ih = (const float*)d_in[3];
    const float* b_hh = (const float*)d_in[4];
    const float* W_fc = (const float*)d_in[5];
    const float* b_fc = (const float*)d_in[6];
    float* out = (float*)d_out;

    cudaFuncSetAttribute(lstm_kernel, cudaFuncAttributeMaxDynamicSharedMemorySize, LSTM_SMEM);
    cudaFuncSetAttribute(gemm_xg_kernel, cudaFuncAttributeMaxDynamicSharedMemorySize, GEMM_SMEM);

    init_kernel<<<256, 256>>>();
    blur_t_kernel<<<(BB * TT * FF) / 256, 256>>>(x);
    blur_f_kernel<<<(BB * TT * FF) / 256, 256>>>();
    gemm_xg_kernel<<<dim3(G4 / 128, (BB * TT) / 128), 256, GEMM_SMEM>>>(W_ih, b_ih, b_hh);
    lstm_kernel<<<NCTA, 256, LSTM_SMEM>>>(W_hh);
    fc_kernel<<<BB, 256>>>(W_fc, b_fc, out);
}

// round 15
// speedup vs baseline: 1.0035x; 1.0035x over previous
#include <cuda_runtime.h>
#include <cstdint>

// ---------------- problem dims ----------------
#define BB 64
#define TT 1024
#define FF 256
#define HH 1024
#define G4 4096
#define OO 256
#define HB (HH * BB)

#define NCTA 128           // persistent CTAs for recurrence (1/SM via SMEM, <=148)
#define JPER 8             // hidden units per CTA (1024/128)

// ---------------- scratch (static device memory only; no allocs) ----------------
__device__ float g_tmp[(size_t)BB * TT * FF];                 // 64 MB  blur pass1
__device__ float g_xb [(size_t)BB * TT * FF];                 // 64 MB  blurred input
__device__ float g_xg [(size_t)BB * TT * G4];                 // 1 GB   gate preactivations (+biases)
__device__ float g_h  [2 * HB];                               // h double buffer, layout [buf][b][k]
__device__ unsigned g_bar;                                    // grid barrier counter (cumulative)

__constant__ float c_w9[9] = {
    1.3383062e-4f, 4.4318616e-3f, 5.3991124e-2f, 2.4197145e-1f,
    3.9894347e-1f,
    2.4197145e-1f, 5.3991124e-2f, 4.4318616e-3f, 1.3383062e-4f
};

// ---------------- helpers ----------------
__device__ __forceinline__ uint32_t f2tf(float x) {           // round-to-nearest tf32
    uint32_t u;
    asm("cvt.rna.tf32.f32 %0, %1;" : "=r"(u) : "f"(x));
    return u;
}
__device__ __forceinline__ void mma_tf32(float* d, uint32_t a0, uint32_t a1,
                                         uint32_t a2, uint32_t a3,
                                         uint32_t b0, uint32_t b1) {
    asm volatile(
        "mma.sync.aligned.m16n8k8.row.col.f32.tf32.tf32.f32 "
        "{%0,%1,%2,%3}, {%4,%5,%6,%7}, {%8,%9}, {%0,%1,%2,%3};"
        : "+f"(d[0]), "+f"(d[1]), "+f"(d[2]), "+f"(d[3])
        : "r"(a0), "r"(a1), "r"(a2), "r"(a3), "r"(b0), "r"(b1));
}
__device__ __forceinline__ void cp16(uint32_t smem_addr, const void* gptr) {
    asm volatile("cp.async.cg.shared.global [%0], [%1], 16;" ::
                 "r"(smem_addr), "l"(gptr));
}

// ---------------- init: zero h0, reset barrier ----------------
__global__ void init_kernel() {
    int i = blockIdx.x * 256 + threadIdx.x;
    if (i < HB) g_h[i] = 0.f;
    if (i == 0) g_bar = 0u;
}

// ---------------- blur time axis ----------------
__global__ void __launch_bounds__(256) blur_t_kernel(const float* __restrict__ x) {
    int idx = blockIdx.x * 256 + threadIdx.x;
    int f = idx & (FF - 1);
    int t = (idx >> 8) & (TT - 1);
    int b = idx >> 18;
    const float* base = x + (size_t)b * TT * FF + f;
    float s = 0.f;
#pragma unroll
    for (int k = 0; k < 9; ++k) {
        int ts = t + k - 4;
        ts = ts < 0 ? 0 : (ts > TT - 1 ? TT - 1 : ts);
        s += c_w9[k] * base[(size_t)ts * FF];
    }
    g_tmp[idx] = s;
}

// ---------------- blur feature axis ----------------
__global__ void __launch_bounds__(256) blur_f_kernel() {
    int idx = blockIdx.x * 256 + threadIdx.x;
    int f = idx & (FF - 1);
    int rowbase = idx - f;
    float s = 0.f;
#pragma unroll
    for (int k = 0; k < 9; ++k) {
        int fs = f + k - 4;
        fs = fs < 0 ? 0 : (fs > FF - 1 ? FF - 1 : fs);
        s += c_w9[k] * g_tmp[rowbase + fs];
    }
    g_xb[idx] = s;
}

// ---------------- xg = xb @ W_ih^T + (b_ih + b_hh), tf32 mma ----------------
// CTA tile 128(m) x 128(n), K=256 in 4 k-tiles of 64. SMEM [row][k] stride 68.
#define GSTR 68
#define GEMM_SMEM (2 * 128 * GSTR * 4)

__global__ void __launch_bounds__(256, 1) gemm_xg_kernel(const float* __restrict__ Wih,
                                                         const float* __restrict__ bih,
                                                         const float* __restrict__ bhh) {
    extern __shared__ float gsm[];
    float* As = gsm;                   // [128][68]
    float* Bs = gsm + 128 * GSTR;      // [128][68]

    const int tid = threadIdx.x;
    const int wrp = tid >> 5, lane = tid & 31;
    const int g = lane >> 2, tig = lane & 3;
    const int ms = wrp & 1, ns = wrp >> 1;
    const int m0 = blockIdx.y * 128;
    const int n0 = blockIdx.x * 128;

    float d[4][4][4];
#pragma unroll
    for (int a = 0; a < 4; ++a)
#pragma unroll
        for (int b = 0; b < 4; ++b)
#pragma unroll
            for (int c = 0; c < 4; ++c) d[a][b][c] = 0.f;

    for (int kt = 0; kt < 4; ++kt) {
        __syncthreads();
#pragma unroll
        for (int p = 0; p < 8; ++p) {
            int idx = p * 256 + tid;               // 2048 float4 units
            int row = idx >> 4, kq = idx & 15;
            float4 va = *(const float4*)&g_xb[(size_t)(m0 + row) * 256 + kt * 64 + kq * 4];
            float4 vb = *(const float4*)&Wih[(size_t)(n0 + row) * 256 + kt * 64 + kq * 4];
            float* pa = &As[row * GSTR + kq * 4];
            pa[0] = __uint_as_float(f2tf(va.x)); pa[1] = __uint_as_float(f2tf(va.y));
            pa[2] = __uint_as_float(f2tf(va.z)); pa[3] = __uint_as_float(f2tf(va.w));
            float* pb = &Bs[row * GSTR + kq * 4];
            pb[0] = __uint_as_float(f2tf(vb.x)); pb[1] = __uint_as_float(f2tf(vb.y));
            pb[2] = __uint_as_float(f2tf(vb.z)); pb[3] = __uint_as_float(f2tf(vb.w));
        }
        __syncthreads();

#pragma unroll
        for (int sc = 0; sc < 2; ++sc) {
            const int kb = sc * 32;
            uint32_t bv[4][8];
#pragma unroll
            for (int nt = 0; nt < 4; ++nt) {
                const float* wp = &Bs[(ns * 32 + nt * 8 + g) * GSTR + kb + 8 * tig];
                *(uint4*)&bv[nt][0] = *(const uint4*)wp;
                *(uint4*)&bv[nt][4] = *(const uint4*)(wp + 4);
            }
#pragma unroll
            for (int mt = 0; mt < 4; ++mt) {
                const float* alo = &As[(ms * 64 + mt * 16 + g) * GSTR + kb + 8 * tig];
                uint32_t al[8], ah[8];
                *(uint4*)&al[0] = *(const uint4*)alo;
                *(uint4*)&al[4] = *(const uint4*)(alo + 4);
                *(uint4*)&ah[0] = *(const uint4*)(alo + 8 * GSTR);
                *(uint4*)&ah[4] = *(const uint4*)(alo + 8 * GSTR + 4);
#pragma unroll
                for (int c = 0; c < 4; ++c)
#pragma unroll
                    for (int nt = 0; nt < 4; ++nt)
                        mma_tf32(d[mt][nt], al[2 * c], ah[2 * c], al[2 * c + 1], ah[2 * c + 1],
                                 bv[nt][2 * c], bv[nt][2 * c + 1]);
            }
        }
    }

    // epilogue: bias + store
#pragma unroll
    for (int nt = 0; nt < 4; ++nt) {
        int n = n0 + ns * 32 + nt * 8 + 2 * tig;
        float bia0 = bih[n] + bhh[n];
        float bia1 = bih[n + 1] + bhh[n + 1];
#pragma unroll
        for (int mt = 0; mt < 4; ++mt) {
            int m = m0 + ms * 64 + mt * 16 + g;
            float2 r0 = make_float2(d[mt][nt][0] + bia0, d[mt][nt][1] + bia1);
            float2 r1 = make_float2(d[mt][nt][2] + bia0, d[mt][nt][3] + bia1);
            *(float2*)&g_xg[(size_t)m * G4 + n]       = r0;
            *(float2*)&g_xg[(size_t)(m + 8) * G4 + n] = r1;
        }
    }
}

// ---------------- persistent LSTM recurrence (tf32 mma) ----------------
// CTA c owns 8 hidden units -> 32 gate rows. Warps: ks = wrp>>1 (k-split 4),
// ms = wrp&1 (batch-split 2). Warp tile: 32(batch) x 32(gates), k-range 256.
// h global layout [b][k] (tf32-rounded). hs staged [b][k_local] stride 132.
// Wsh [n(32)][k(1024)] stride 1028. red [ks(4)][b(64)][n(32)] stride 40 (alias buf0).
#define WSTR 1028
#define HSTR 132
#define RSTR 40
#define BUFV 10240                                 // floats per h stage buffer
#define WSH_FLOATS (32 * WSTR)                     // 32896
#define LSTM_SMEM ((WSH_FLOATS + 2 * BUFV) * 4)    // 213504 B

__global__ void __launch_bounds__(256, 1) lstm_kernel(const float* __restrict__ Whh) {
    extern __shared__ __align__(16) float sm[];
    float* Wsh  = sm;
    float* bufs = sm + WSH_FLOATS;                 // two BUFV buffers
    float* red  = bufs;                            // aliases buf0

    const int tid  = threadIdx.x;
    const int lane = tid & 31, wrp = tid >> 5;
    const int g = lane >> 2, tig = lane & 3;
    const int ks = wrp >> 1, ms = wrp & 1;
    const int j0 = blockIdx.x * JPER;

    // one-time: W slice -> SMEM [n][k], tf32-rounded
    for (int i = tid; i < 32 * 1024; i += 256) {
        int n = i >> 10, k = i & 1023;
        int q = n >> 3, jj = n & 7;
        Wsh[n * WSTR + k] = __uint_as_float(f2tf(Whh[(size_t)(q * HH + j0 + jj) * HH + k]));
    }
    __syncthreads();

    float cst[2] = {0.f, 0.f};
    const int cell0 = tid * 2;
    const int jj0 = cell0 >> 6, b0 = cell0 & 63;   // cell1 = (jj0, b0+1)

    for (int t = 0; t < TT; ++t) {
        const float* hbuf = g_h + (size_t)(t & 1) * HB;
        float* hout       = g_h + (size_t)((t + 1) & 1) * HB;

        // prefetch xg for this step's cells
        float xgv[2][4];
#pragma unroll
        for (int cc = 0; cc < 2; ++cc)
#pragma unroll
            for (int q = 0; q < 4; ++q)
                xgv[cc][q] = g_xg[((size_t)(b0 + cc) * TT + t) * G4 + q * HH + j0 + jj0];

        float d[2][4][4];
#pragma unroll
        for (int a = 0; a < 2; ++a)
#pragma unroll
            for (int b = 0; b < 4; ++b)
#pragma unroll
                for (int c = 0; c < 4; ++c) d[a][b][c] = 0.f;

        // stage chunk 0
        {
#pragma unroll
            for (int p = 0; p < 8; ++p) {
                int idx = p * 256 + tid;
                int b = idx >> 5, kq = idx & 31;
                uint32_t dst = (uint32_t)__cvta_generic_to_shared(&bufs[b * HSTR + kq * 4]);
                cp16(dst, hbuf + (size_t)b * HH + kq * 4);
            }
            asm volatile("cp.async.commit_group;");
        }

        for (int ch = 0; ch < 8; ++ch) {
            asm volatile("cp.async.wait_group 0;");
            __syncthreads();
            if (ch < 7) {
                float* nbuf = bufs + ((ch + 1) & 1) * BUFV;
#pragma unroll
                for (int p = 0; p < 8; ++p) {
                    int idx = p * 256 + tid;
                    int b = idx >> 5, kq = idx & 31;
                    uint32_t dst = (uint32_t)__cvta_generic_to_shared(&nbuf[b * HSTR + kq * 4]);
                    cp16(dst, hbuf + (size_t)b * HH + (ch + 1) * 128 + kq * 4);
                }
                asm volatile("cp.async.commit_group;");
            }
            // compute on buf[ch&1], warp k-range = ks*32 within the 128-chunk
            const float* buf = bufs + (ch & 1) * BUFV;
            const int kb = ks * 32;
            const int kgl = ch * 128 + kb;

            uint32_t bv[4][8];
#pragma unroll
            for (int nt = 0; nt < 4; ++nt) {
                const float* wp = &Wsh[(nt * 8 + g) * WSTR + kgl + 8 * tig];
                *(uint4*)&bv[nt][0] = *(const uint4*)wp;
                *(uint4*)&bv[nt][4] = *(const uint4*)(wp + 4);
            }
#pragma unroll
            for (int mt = 0; mt < 2; ++mt) {
                const float* alo = &buf[(ms * 32 + mt * 16 + g) * HSTR + kb + 8 * tig];
                uint32_t al[8], ah[8];
                *(uint4*)&al[0] = *(const uint4*)alo;
                *(uint4*)&al[4] = *(const uint4*)(alo + 4);
                *(uint4*)&ah[0] = *(const uint4*)(alo + 8 * HSTR);
                *(uint4*)&ah[4] = *(const uint4*)(alo + 8 * HSTR + 4);
#pragma unroll
                for (int c = 0; c < 4; ++c)
#pragma unroll
                    for (int nt = 0; nt < 4; ++nt)
                        mma_tf32(d[mt][nt], al[2 * c], ah[2 * c], al[2 * c + 1], ah[2 * c + 1],
                                 bv[nt][2 * c], bv[nt][2 * c + 1]);
            }
        }
        __syncthreads();                           // all buf reads done (incl. buf0)

        // write partials to red[ks][b][n]
#pragma unroll
        for (int mt = 0; mt < 2; ++mt)
#pragma unroll
            for (int nt = 0; nt < 4; ++nt) {
                int m = ms * 32 + mt * 16 + g;
                int n = nt * 8 + 2 * tig;
                float* base = &red[(ks * 64 + m) * RSTR + n];
                *(float2*)base              = make_float2(d[mt][nt][0], d[mt][nt][1]);
                *(float2*)(base + 8 * RSTR) = make_float2(d[mt][nt][2], d[mt][nt][3]);
            }
        __syncthreads();

        // gates: 2 cells per thread
#pragma unroll
        for (int cc = 0; cc < 2; ++cc) {
            int b = b0 + cc;
            float gp[4];
#pragma unroll
            for (int q = 0; q < 4; ++q) {
                float s = 0.f;
#pragma unroll
                for (int kss = 0; kss < 4; ++kss)
                    s += red[(kss * 64 + b) * RSTR + q * 8 + jj0];
                gp[q] = s + xgv[cc][q];
            }
            float iv = 1.f / (1.f + expf(-gp[0]));
            float fv = 1.f / (1.f + expf(-gp[1]));
            float gv = tanhf(gp[2]);
            float ov = 1.f / (1.f + expf(-gp[3]));
            float cnew = fv * cst[cc] + iv * gv;
            cst[cc] = cnew;
            float hval = ov * tanhf(cnew);
            hout[(size_t)b * HH + j0 + jj0] = __uint_as_float(f2tf(hval));
        }

        // grid barrier
        __syncthreads();
        if (tid == 0) {
            __threadfence();
            atomicAdd(&g_bar, 1u);
            unsigned target = (unsigned)(t + 1) * (unsigned)NCTA;
            while (atomicAdd(&g_bar, 0u) < target) { __nanosleep(64); }
            __threadfence();
        }
        __syncthreads();
    }
}

// ---------------- out = h_last @ W_fc^T + b_fc ----------------
__global__ void __launch_bounds__(256) fc_kernel(const float* __restrict__ Wfc,
                                                 const float* __restrict__ bfc,
                                                 float* __restrict__ out) {
    __shared__ float hsm[HH];
    const int b = blockIdx.x;
    const int tid = threadIdx.x;
    const float* hbuf = g_h;                       // final h in buffer 0 (T even), [b][k]
    for (int k = tid; k < HH; k += 256) hsm[k] = hbuf[(size_t)b * HH + k];
    __syncthreads();
    const int wrp = tid >> 5, lane = tid & 31;
    for (int o = wrp; o < OO; o += 8) {
        float s = 0.f;
        for (int k = lane; k < HH; k += 32) s += hsm[k] * Wfc[(size_t)o * HH + k];
#pragma unroll
        for (int off = 16; off; off >>= 1) s += __shfl_xor_sync(0xffffffffu, s, off);
        if (lane == 0) out[b * OO + o] = s + bfc[o];
    }
}

// ---------------- launch ----------------
extern "C" void kernel_launch(void* const* d_in, const int* in_sizes, int n_in,
                              void* d_out, int out_size) {
    const float* x    = (const float*)d_in[0];
    const float* W_ih = (const float*)d_in[1];
    const float* W_hh = (const float*)d_in[2];
    const float* b_ih = (const float*)d_in[3];
    const float* b_hh = (const float*)d_in[4];
    const float* W_fc = (const float*)d_in[5];
    const float* b_fc = (const float*)d_in[6];
    float* out = (float*)d_out;

    cudaFuncSetAttribute(lstm_kernel, cudaFuncAttributeMaxDynamicSharedMemorySize, LSTM_SMEM);
    cudaFuncSetAttribute(gemm_xg_kernel, cudaFuncAttributeMaxDynamicSharedMemorySize, GEMM_SMEM);

    init_kernel<<<256, 256>>>();
    blur_t_kernel<<<(BB * TT * FF) / 256, 256>>>(x);
    blur_f_kernel<<<(BB * TT * FF) / 256, 256>>>();
    gemm_xg_kernel<<<dim3(G4 / 128, (BB * TT) / 128), 256, GEMM_SMEM>>>(W_ih, b_ih, b_hh);
    lstm_kernel<<<NCTA, 256, LSTM_SMEM>>>(W_hh);
    fc_kernel<<<BB, 256>>>(W_fc, b_fc, out);
}

// round 16
// speedup vs baseline: 1.0051x; 1.0016x over previous
#include <cuda_runtime.h>
#include <cstdint>

// ---------------- problem dims ----------------
#define BB 64
#define TT 1024
#define FF 256
#define HH 1024
#define G4 4096
#define OO 256
#define HB (HH * BB)

#define NCTA 128           // persistent CTAs for recurrence (1/SM via SMEM, <=148)
#define JPER 8             // hidden units per CTA (1024/128)

// ---------------- scratch (static device memory only; no allocs) ----------------
__device__ float g_tmp[(size_t)BB * TT * FF];                 // 64 MB  blur pass1
__device__ float g_xb [(size_t)BB * TT * FF];                 // 64 MB  blurred input
__device__ float g_xg [(size_t)BB * TT * G4];                 // 1 GB   gate preactivations (+biases)
__device__ float g_h  [2 * HB];                               // h double buffer, layout [buf][b][k]
__device__ unsigned g_bar;                                    // grid barrier counter (cumulative)

__constant__ float c_w9[9] = {
    1.3383062e-4f, 4.4318616e-3f, 5.3991124e-2f, 2.4197145e-1f,
    3.9894347e-1f,
    2.4197145e-1f, 5.3991124e-2f, 4.4318616e-3f, 1.3383062e-4f
};

// ---------------- helpers ----------------
__device__ __forceinline__ uint32_t f2tf(float x) {           // round-to-nearest tf32
    uint32_t u;
    asm("cvt.rna.tf32.f32 %0, %1;" : "=r"(u) : "f"(x));
    return u;
}
__device__ __forceinline__ void mma_tf32(float* d, uint32_t a0, uint32_t a1,
                                         uint32_t a2, uint32_t a3,
                                         uint32_t b0, uint32_t b1) {
    asm volatile(
        "mma.sync.aligned.m16n8k8.row.col.f32.tf32.tf32.f32 "
        "{%0,%1,%2,%3}, {%4,%5,%6,%7}, {%8,%9}, {%0,%1,%2,%3};"
        : "+f"(d[0]), "+f"(d[1]), "+f"(d[2]), "+f"(d[3])
        : "r"(a0), "r"(a1), "r"(a2), "r"(a3), "r"(b0), "r"(b1));
}
__device__ __forceinline__ void cp16(uint32_t smem_addr, const void* gptr) {
    asm volatile("cp.async.cg.shared.global [%0], [%1], 16;" ::
                 "r"(smem_addr), "l"(gptr));
}

// ---------------- init: zero h0, reset barrier ----------------
__global__ void init_kernel() {
    int i = blockIdx.x * 256 + threadIdx.x;
    if (i < HB) g_h[i] = 0.f;
    if (i == 0) g_bar = 0u;
}

// ---------------- blur time axis ----------------
__global__ void __launch_bounds__(256) blur_t_kernel(const float* __restrict__ x) {
    int idx = blockIdx.x * 256 + threadIdx.x;
    int f = idx & (FF - 1);
    int t = (idx >> 8) & (TT - 1);
    int b = idx >> 18;
    const float* base = x + (size_t)b * TT * FF + f;
    float s = 0.f;
#pragma unroll
    for (int k = 0; k < 9; ++k) {
        int ts = t + k - 4;
        ts = ts < 0 ? 0 : (ts > TT - 1 ? TT - 1 : ts);
        s += c_w9[k] * base[(size_t)ts * FF];
    }
    g_tmp[idx] = s;
}

// ---------------- blur feature axis ----------------
__global__ void __launch_bounds__(256) blur_f_kernel() {
    int idx = blockIdx.x * 256 + threadIdx.x;
    int f = idx & (FF - 1);
    int rowbase = idx - f;
    float s = 0.f;
#pragma unroll
    for (int k = 0; k < 9; ++k) {
        int fs = f + k - 4;
        fs = fs < 0 ? 0 : (fs > FF - 1 ? FF - 1 : fs);
        s += c_w9[k] * g_tmp[rowbase + fs];
    }
    g_xb[idx] = s;
}

// ---------------- xg = xb @ W_ih^T + (b_ih + b_hh), tf32 mma ----------------
// CTA tile 128(m) x 128(n), K=256 in 4 k-tiles of 64. SMEM [row][k] stride 68.
#define GSTR 68
#define GEMM_SMEM (2 * 128 * GSTR * 4)

__global__ void __launch_bounds__(256, 1) gemm_xg_kernel(const float* __restrict__ Wih,
                                                         const float* __restrict__ bih,
                                                         const float* __restrict__ bhh) {
    extern __shared__ float gsm[];
    float* As = gsm;                   // [128][68]
    float* Bs = gsm + 128 * GSTR;      // [128][68]

    const int tid = threadIdx.x;
    const int wrp = tid >> 5, lane = tid & 31;
    const int g = lane >> 2, tig = lane & 3;
    const int ms = wrp & 1, ns = wrp >> 1;
    const int m0 = blockIdx.y * 128;
    const int n0 = blockIdx.x * 128;

    float d[4][4][4];
#pragma unroll
    for (int a = 0; a < 4; ++a)
#pragma unroll
        for (int b = 0; b < 4; ++b)
#pragma unroll
            for (int c = 0; c < 4; ++c) d[a][b][c] = 0.f;

    for (int kt = 0; kt < 4; ++kt) {
        __syncthreads();
#pragma unroll
        for (int p = 0; p < 8; ++p) {
            int idx = p * 256 + tid;               // 2048 float4 units
            int row = idx >> 4, kq = idx & 15;
            float4 va = *(const float4*)&g_xb[(size_t)(m0 + row) * 256 + kt * 64 + kq * 4];
            float4 vb = *(const float4*)&Wih[(size_t)(n0 + row) * 256 + kt * 64 + kq * 4];
            float* pa = &As[row * GSTR + kq * 4];
            pa[0] = __uint_as_float(f2tf(va.x)); pa[1] = __uint_as_float(f2tf(va.y));
            pa[2] = __uint_as_float(f2tf(va.z)); pa[3] = __uint_as_float(f2tf(va.w));
            float* pb = &Bs[row * GSTR + kq * 4];
            pb[0] = __uint_as_float(f2tf(vb.x)); pb[1] = __uint_as_float(f2tf(vb.y));
            pb[2] = __uint_as_float(f2tf(vb.z)); pb[3] = __uint_as_float(f2tf(vb.w));
        }
        __syncthreads();

#pragma unroll
        for (int sc = 0; sc < 2; ++sc) {
            const int kb = sc * 32;
            uint32_t bv[4][8];
#pragma unroll
            for (int nt = 0; nt < 4; ++nt) {
                const float* wp = &Bs[(ns * 32 + nt * 8 + g) * GSTR + kb + 8 * tig];
                *(uint4*)&bv[nt][0] = *(const uint4*)wp;
                *(uint4*)&bv[nt][4] = *(const uint4*)(wp + 4);
            }
#pragma unroll
            for (int mt = 0; mt < 4; ++mt) {
                const float* alo = &As[(ms * 64 + mt * 16 + g) * GSTR + kb + 8 * tig];
                uint32_t al[8], ah[8];
                *(uint4*)&al[0] = *(const uint4*)alo;
                *(uint4*)&al[4] = *(const uint4*)(alo + 4);
                *(uint4*)&ah[0] = *(const uint4*)(alo + 8 * GSTR);
                *(uint4*)&ah[4] = *(const uint4*)(alo + 8 * GSTR + 4);
#pragma unroll
                for (int c = 0; c < 4; ++c)
#pragma unroll
                    for (int nt = 0; nt < 4; ++nt)
                        mma_tf32(d[mt][nt], al[2 * c], ah[2 * c], al[2 * c + 1], ah[2 * c + 1],
                                 bv[nt][2 * c], bv[nt][2 * c + 1]);
            }
        }
    }

    // epilogue: bias + store
#pragma unroll
    for (int nt = 0; nt < 4; ++nt) {
        int n = n0 + ns * 32 + nt * 8 + 2 * tig;
        float bia0 = bih[n] + bhh[n];
        float bia1 = bih[n + 1] + bhh[n + 1];
#pragma unroll
        for (int mt = 0; mt < 4; ++mt) {
            int m = m0 + ms * 64 + mt * 16 + g;
            float2 r0 = make_float2(d[mt][nt][0] + bia0, d[mt][nt][1] + bia1);
            float2 r1 = make_float2(d[mt][nt][2] + bia0, d[mt][nt][3] + bia1);
            *(float2*)&g_xg[(size_t)m * G4 + n]       = r0;
            *(float2*)&g_xg[(size_t)(m + 8) * G4 + n] = r1;
        }
    }
}

// ---------------- persistent LSTM recurrence (tf32 mma) ----------------
// CTA c owns 8 hidden units -> 32 gate rows. Warps: ks = wrp>>1 (k-split 4),
// ms = wrp&1 (batch-split 2). Warp tile: 32(batch) x 32(gates), k-range 256.
// h global layout [b][k] (tf32-rounded). hs staged [b][k_local] stride 132.
// Wsh [n(32)][k(1024)] stride 1028. red [ks(4)][b(64)][n(32)] stride 40 (alias buf0).
#define WSTR 1028
#define HSTR 132
#define RSTR 40
#define BUFV 10240                                 // floats per h stage buffer
#define WSH_FLOATS (32 * WSTR)                     // 32896
#define LSTM_SMEM ((WSH_FLOATS + 2 * BUFV) * 4)    // 213504 B

__global__ void __launch_bounds__(256, 1) lstm_kernel(const float* __restrict__ Whh) {
    extern __shared__ __align__(16) float sm[];
    float* Wsh  = sm;
    float* bufs = sm + WSH_FLOATS;                 // two BUFV buffers
    float* red  = bufs;                            // aliases buf0

    const int tid  = threadIdx.x;
    const int lane = tid & 31, wrp = tid >> 5;
    const int g = lane >> 2, tig = lane & 3;
    const int ks = wrp >> 1, ms = wrp & 1;
    const int j0 = blockIdx.x * JPER;

    // one-time: W slice -> SMEM [n][k], tf32-rounded
    for (int i = tid; i < 32 * 1024; i += 256) {
        int n = i >> 10, k = i & 1023;
        int q = n >> 3, jj = n & 7;
        Wsh[n * WSTR + k] = __uint_as_float(f2tf(Whh[(size_t)(q * HH + j0 + jj) * HH + k]));
    }
    __syncthreads();

    float cst[2] = {0.f, 0.f};
    const int cell0 = tid * 2;
    const int jj0 = cell0 >> 6, b0 = cell0 & 63;   // cell1 = (jj0, b0+1)

    for (int t = 0; t < TT; ++t) {
        const float* hbuf = g_h + (size_t)(t & 1) * HB;
        float* hout       = g_h + (size_t)((t + 1) & 1) * HB;

        // prefetch xg for this step's cells
        float xgv[2][4];
#pragma unroll
        for (int cc = 0; cc < 2; ++cc)
#pragma unroll
            for (int q = 0; q < 4; ++q)
                xgv[cc][q] = g_xg[((size_t)(b0 + cc) * TT + t) * G4 + q * HH + j0 + jj0];

        float d[2][4][4];
#pragma unroll
        for (int a = 0; a < 2; ++a)
#pragma unroll
            for (int b = 0; b < 4; ++b)
#pragma unroll
                for (int c = 0; c < 4; ++c) d[a][b][c] = 0.f;

        // stage chunk 0
        {
#pragma unroll
            for (int p = 0; p < 8; ++p) {
                int idx = p * 256 + tid;
                int b = idx >> 5, kq = idx & 31;
                uint32_t dst = (uint32_t)__cvta_generic_to_shared(&bufs[b * HSTR + kq * 4]);
                cp16(dst, hbuf + (size_t)b * HH + kq * 4);
            }
            asm volatile("cp.async.commit_group;");
        }

        for (int ch = 0; ch < 8; ++ch) {
            asm volatile("cp.async.wait_group 0;");
            __syncthreads();
            if (ch < 7) {
                float* nbuf = bufs + ((ch + 1) & 1) * BUFV;
#pragma unroll
                for (int p = 0; p < 8; ++p) {
                    int idx = p * 256 + tid;
                    int b = idx >> 5, kq = idx & 31;
                    uint32_t dst = (uint32_t)__cvta_generic_to_shared(&nbuf[b * HSTR + kq * 4]);
                    cp16(dst, hbuf + (size_t)b * HH + (ch + 1) * 128 + kq * 4);
                }
                asm volatile("cp.async.commit_group;");
            }
            // compute on buf[ch&1], warp k-range = ks*32 within the 128-chunk
            const float* buf = bufs + (ch & 1) * BUFV;
            const int kb = ks * 32;
            const int kgl = ch * 128 + kb;

            uint32_t bv[4][8];
#pragma unroll
            for (int nt = 0; nt < 4; ++nt) {
                const float* wp = &Wsh[(nt * 8 + g) * WSTR + kgl + 8 * tig];
                *(uint4*)&bv[nt][0] = *(const uint4*)wp;
                *(uint4*)&bv[nt][4] = *(const uint4*)(wp + 4);
            }
#pragma unroll
            for (int mt = 0; mt < 2; ++mt) {
                const float* alo = &buf[(ms * 32 + mt * 16 + g) * HSTR + kb + 8 * tig];
                uint32_t al[8], ah[8];
                *(uint4*)&al[0] = *(const uint4*)alo;
                *(uint4*)&al[4] = *(const uint4*)(alo + 4);
                *(uint4*)&ah[0] = *(const uint4*)(alo + 8 * HSTR);
                *(uint4*)&ah[4] = *(const uint4*)(alo + 8 * HSTR + 4);
#pragma unroll
                for (int c = 0; c < 4; ++c)
#pragma unroll
                    for (int nt = 0; nt < 4; ++nt)
                        mma_tf32(d[mt][nt], al[2 * c], ah[2 * c], al[2 * c + 1], ah[2 * c + 1],
                                 bv[nt][2 * c], bv[nt][2 * c + 1]);
            }
        }
        __syncthreads();                           // all buf reads done (incl. buf0)

        // write partials to red[ks][b][n]
#pragma unroll
        for (int mt = 0; mt < 2; ++mt)
#pragma unroll
            for (int nt = 0; nt < 4; ++nt) {
                int m = ms * 32 + mt * 16 + g;
                int n = nt * 8 + 2 * tig;
                float* base = &red[(ks * 64 + m) * RSTR + n];
                *(float2*)base              = make_float2(d[mt][nt][0], d[mt][nt][1]);
                *(float2*)(base + 8 * RSTR) = make_float2(d[mt][nt][2], d[mt][nt][3]);
            }
        __syncthreads();

        // gates: 2 cells per thread
#pragma unroll
        for (int cc = 0; cc < 2; ++cc) {
            int b = b0 + cc;
            float gp[4];
#pragma unroll
            for (int q = 0; q < 4; ++q) {
                float s = 0.f;
#pragma unroll
                for (int kss = 0; kss < 4; ++kss)
                    s += red[(kss * 64 + b) * RSTR + q * 8 + jj0];
                gp[q] = s + xgv[cc][q];
            }
            float iv = 1.f / (1.f + expf(-gp[0]));
            float fv = 1.f / (1.f + expf(-gp[1]));
            float gv = tanhf(gp[2]);
            float ov = 1.f / (1.f + expf(-gp[3]));
            float cnew = fv * cst[cc] + iv * gv;
            cst[cc] = cnew;
            float hval = ov * tanhf(cnew);
            hout[(size_t)b * HH + j0 + jj0] = __uint_as_float(f2tf(hval));
        }

        // grid barrier
        __syncthreads();
        if (tid == 0) {
            __threadfence();
            atomicAdd(&g_bar, 1u);
            unsigned target = (unsigned)(t + 1) * (unsigned)NCTA;
            while (atomicAdd(&g_bar, 0u) < target) { __nanosleep(64); }
            __threadfence();
        }
        __syncthreads();
    }
}

// ---------------- out = h_last @ W_fc^T + b_fc ----------------
__global__ void __launch_bounds__(256) fc_kernel(const float* __restrict__ Wfc,
                                                 const float* __restrict__ bfc,
                                                 float* __restrict__ out) {
    __shared__ float hsm[HH];
    const int b = blockIdx.x;
    const int tid = threadIdx.x;
    const float* hbuf = g_h;                       // final h in buffer 0 (T even), [b][k]
    for (int k = tid; k < HH; k += 256) hsm[k] = hbuf[(size_t)b * HH + k];
    __syncthreads();
    const int wrp = tid >> 5, lane = tid & 31;
    for (int o = wrp; o < OO; o += 8) {
        float s = 0.f;
        for (int k = lane; k < HH; k += 32) s += hsm[k] * Wfc[(size_t)o * HH + k];
#pragma unroll
        for (int off = 16; off; off >>= 1) s += __shfl_xor_sync(0xffffffffu, s, off);
        if (lane == 0) out[b * OO + o] = s + bfc[o];
    }
}

// ---------------- launch ----------------
extern "C" void kernel_launch(void* const* d_in, const int* in_sizes, int n_in,
                              void* d_out, int out_size) {
    const float* x    = (const float*)d_in[0];
    const float* W_ih = (const float*)d_in[1];
    const float* W_hh = (const float*)d_in[2];
    const float* b_ih = (const float*)d_in[3];
    const float* b_hh = (const float*)d_in[4];
    const float* W_fc = (const float*)d_in[5];
    const float* b_fc = (const float*)d_in[6];
    float* out = (float*)d_out;

    cudaFuncSetAttribute(lstm_kernel, cudaFuncAttributeMaxDynamicSharedMemorySize, LSTM_SMEM);
    cudaFuncSetAttribute(gemm_xg_kernel, cudaFuncAttributeMaxDynamicSharedMemorySize, GEMM_SMEM);

    init_kernel<<<256, 256>>>();
    blur_t_kernel<<<(BB * TT * FF) / 256, 256>>>(x);
    blur_f_kernel<<<(BB * TT * FF) / 256, 256>>>();
    gemm_xg_kernel<<<dim3(G4 / 128, (BB * TT) / 128), 256, GEMM_SMEM>>>(W_ih, b_ih, b_hh);
    lstm_kernel<<<NCTA, 256, LSTM_SMEM>>>(W_hh);
    fc_kernel<<<BB, 256>>>(W_fc, b_fc, out);
}